// round 7
// baseline (speedup 1.0000x reference)
#include <cuda_runtime.h>
#include <cuda_bf16.h>
#include <stdint.h>
#include <math.h>

// Problem constants
#define BQ     16
#define QL     30
#define DSEQ   65          // cls + 64 chunk tokens
#define NTOK   (BQ*QL + BQ*DSEQ)   // 1520
#define NTOKP  1536                 // padded
#define DMODEL 768
#define NH     8
#define HD     96
#define FFD    3072
#define QKVD   2304

// ---------------- scratch (static device globals) ----------------
__device__ float g_X   [NTOKP * DMODEL];
__device__ float g_X0q [BQ * DMODEL];
__device__ float g_QKV [NTOKP * QKVD];
__device__ float g_ATT [NTOKP * DMODEL];
__device__ float g_TMP [NTOKP * DMODEL];
__device__ float g_H   [NTOKP * FFD];
__device__ float g_PV  [32 * DMODEL];
// pre-split (hi,lo) tf32 buffers
__device__ uint2 g_WqkvSP[2 * DMODEL * QKVD];
__device__ uint2 g_WoSP  [2 * DMODEL * DMODEL];
__device__ uint2 g_W1SP  [2 * DMODEL * FFD];
__device__ uint2 g_W2SP  [2 * FFD * DMODEL];
__device__ uint2 g_ACT   [NTOKP * FFD];

// ---------------- helpers ----------------
__device__ __forceinline__ void cp16(void* smem, const void* g) {
    uint32_t s = (uint32_t)__cvta_generic_to_shared(smem);
    asm volatile("cp.async.ca.shared.global [%0], [%1], 16;" :: "r"(s), "l"(g));
}
__device__ __forceinline__ void f32split(float x, uint32_t& hi, uint32_t& lo) {
    uint32_t h, l;
    asm("cvt.rna.tf32.f32 %0, %1;" : "=r"(h) : "f"(x));
    float hf = __uint_as_float(h);
    asm("cvt.rna.tf32.f32 %0, %1;" : "=r"(l) : "f"(x - hf));
    hi = h; lo = l;
}
__device__ __forceinline__ void mma8(float* c, const uint32_t* a, const uint32_t* b) {
    asm volatile("mma.sync.aligned.m16n8k8.row.col.f32.tf32.tf32.f32 "
                 "{%0,%1,%2,%3}, {%4,%5,%6,%7}, {%8,%9}, {%0,%1,%2,%3};"
                 : "+f"(c[0]), "+f"(c[1]), "+f"(c[2]), "+f"(c[3])
                 : "r"(a[0]), "r"(a[1]), "r"(a[2]), "r"(a[3]),
                   "r"(b[0]), "r"(b[1]));
}
__device__ __forceinline__ float gelu_f(float x) {
    return 0.5f * x * (1.f + tanhf(0.7978845608028654f * (x + 0.044715f * x * x * x)));
}

// ---------------- split: f32 -> (tf32 hi, tf32 lo) interleaved ----------------
__global__ void split_kernel(const float* __restrict__ in, uint2* __restrict__ out, int n)
{
    int i = (blockIdx.x * 256 + threadIdx.x) * 4;
    if (i >= n) return;
    float4 v = *reinterpret_cast<const float4*>(in + i);
    uint4 o1, o2;
    f32split(v.x, o1.x, o1.y); f32split(v.y, o1.z, o1.w);
    f32split(v.z, o2.x, o2.y); f32split(v.w, o2.z, o2.w);
    uint4* op = reinterpret_cast<uint4*>(out + i);
    op[0] = o1; op[1] = o2;
}

// ---------------- embedding / sequence assembly ----------------
__global__ void embed_kernel(const float* __restrict__ emb,
                             const float* __restrict__ pos_q,
                             const float* __restrict__ pos_d,
                             const float* __restrict__ cls_topic,
                             const int*   __restrict__ query,
                             const int*   __restrict__ document,
                             float* __restrict__ X, float* __restrict__ X0q)
{
    int r = blockIdx.x;
    int tid = threadIdx.x;                  // 256 threads
    float* xr = X + (size_t)r * DMODEL;
    if (r < BQ * QL) {
        int b = r / QL, t = r % QL;
        const float* e = emb + (size_t)query[b * QL + t] * DMODEL;
        const float* p = pos_q + (size_t)t * DMODEL;
        for (int k = tid; k < DMODEL; k += 256) {
            float v = e[k] + p[k];
            xr[k] = v;
            if (t == 0) X0q[(size_t)b * DMODEL + k] = v;
        }
    } else {
        int rr = r - BQ * QL;
        int b = rr / DSEQ, p = rr % DSEQ;
        if (p == 0) {
            for (int k = tid; k < DMODEL; k += 256) xr[k] = cls_topic[k];
        } else if (p < 8) {
            for (int k = tid; k < DMODEL; k += 256) xr[k] = 0.f;
        } else {
            int t = p - 8;
            const float* e = emb + (size_t)document[b * 2000 + t] * DMODEL;
            const float* pp = pos_d + (size_t)t * DMODEL;
            for (int k = tid; k < DMODEL; k += 256) xr[k] = e[k] + pp[k];
        }
    }
}

// ---------------- tensor-core GEMM on pre-split operands ----------------
// C[M,N] = A[M,K] @ B[K,N] (+bias)(+res)(gelu), 3xTF32.
// A,B are (hi,lo) uint2 arrays. Tile 64x64x16, 256 threads (8 warps, 4x2).
template<bool GELU, bool RES>
__global__ void __launch_bounds__(256)
gemm_ts(const uint2* __restrict__ A, const uint2* __restrict__ B,
        const float* __restrict__ bias, const float* __restrict__ Rsd,
        float* __restrict__ C, int M, int N, int K)
{
    __shared__ uint2 As[2][64][20];    // [m][k], pad->20: conflict-free LDS.64
    __shared__ uint2 Bs[2][16][68];    // [k][n], pad->68: conflict-free LDS.64

    const int tid  = threadIdx.x;
    const int lane = tid & 31, warp = tid >> 5;
    const int wm = warp >> 1, wn = warp & 1;
    const int g  = lane >> 2, tg = lane & 3;
    const int bm = blockIdx.y * 64, bn = blockIdx.x * 64;

    const int ar = tid >> 2, aseg = (tid & 3) * 2;      // A: row, k-u2 offset {0,2,4,6}
    const int br = tid >> 4, bseg = (tid & 15) * 2;     // B: k-row, n-u2 offset {0..30}

    float acc[4][4];
#pragma unroll
    for (int j = 0; j < 4; j++)
#pragma unroll
        for (int q = 0; q < 4; q++) acc[j][q] = 0.f;

    const int KT = K >> 4;

    {   // prologue
        const uint2* ap = A + (size_t)(bm + ar) * K;
        cp16(&As[0][ar][aseg],     ap + aseg);
        cp16(&As[0][ar][aseg + 8], ap + aseg + 8);
        const uint2* bp = B + (size_t)br * N + bn;
        cp16(&Bs[0][br][bseg],      bp + bseg);
        cp16(&Bs[0][br][bseg + 32], bp + bseg + 32);
        asm volatile("cp.async.commit_group;");
    }

    for (int kt = 0; kt < KT; kt++) {
        const int buf = kt & 1;
        if (kt + 1 < KT) {
            const int k0 = (kt + 1) << 4;
            const uint2* ap = A + (size_t)(bm + ar) * K + k0;
            cp16(&As[buf ^ 1][ar][aseg],     ap + aseg);
            cp16(&As[buf ^ 1][ar][aseg + 8], ap + aseg + 8);
            const uint2* bp = B + (size_t)(k0 + br) * N + bn;
            cp16(&Bs[buf ^ 1][br][bseg],      bp + bseg);
            cp16(&Bs[buf ^ 1][br][bseg + 32], bp + bseg + 32);
            asm volatile("cp.async.commit_group;");
            asm volatile("cp.async.wait_group 1;");
        } else {
            asm volatile("cp.async.wait_group 0;");
        }
        __syncthreads();

#pragma unroll
        for (int ks = 0; ks < 2; ks++) {
            const int k8 = ks * 8;
            const int mb = wm * 16;
            uint2 a0 = As[buf][mb + g    ][k8 + tg    ];
            uint2 a1 = As[buf][mb + g + 8][k8 + tg    ];
            uint2 a2 = As[buf][mb + g    ][k8 + tg + 4];
            uint2 a3 = As[buf][mb + g + 8][k8 + tg + 4];
            uint32_t ahi[4] = {a0.x, a1.x, a2.x, a3.x};
            uint32_t alo[4] = {a0.y, a1.y, a2.y, a3.y};
#pragma unroll
            for (int nf = 0; nf < 4; nf++) {
                const int nb = wn * 32 + nf * 8 + g;
                uint2 b0 = Bs[buf][k8 + tg    ][nb];
                uint2 b1 = Bs[buf][k8 + tg + 4][nb];
                uint32_t bh[2] = {b0.x, b1.x};
                uint32_t bl[2] = {b0.y, b1.y};
                mma8(acc[nf], ahi, bh);
                mma8(acc[nf], ahi, bl);
                mma8(acc[nf], alo, bh);
            }
        }
        __syncthreads();
    }

    // epilogue
#pragma unroll
    for (int nf = 0; nf < 4; nf++) {
        const int c0 = bn + wn * 32 + nf * 8 + 2 * tg;
#pragma unroll
        for (int half = 0; half < 2; half++) {
            const int r = bm + wm * 16 + g + half * 8;
            if (r < M) {
                float v0 = acc[nf][half * 2 + 0] + bias[c0];
                float v1 = acc[nf][half * 2 + 1] + bias[c0 + 1];
                if (RES) { v0 += Rsd[(size_t)r * N + c0]; v1 += Rsd[(size_t)r * N + c0 + 1]; }
                if (GELU) { v0 = gelu_f(v0); v1 = gelu_f(v1); }
                *reinterpret_cast<float2*>(&C[(size_t)r * N + c0]) = make_float2(v0, v1);
            }
        }
    }
}

// ---------------- attention: one block per (sequence, head) ----------------
__global__ void attn_kernel(const float* __restrict__ QKV, float* __restrict__ ATT)
{
    __shared__ float Ks[65 * 97];
    __shared__ float Qs[4][96];
    __shared__ float Pw[4][68];
    int s = blockIdx.x;        // 0..31
    int h = blockIdx.y;        // 0..7
    int tid = threadIdx.x;     // 128
    int warp = tid >> 5, lane = tid & 31;

    int start, len;
    if (s < BQ) { start = QL * s; len = QL; }
    else        { start = BQ * QL + DSEQ * (s - BQ); len = DSEQ; }

    for (int idx = tid; idx < len * HD; idx += 128) {
        int r = idx / HD, c = idx % HD;
        Ks[r * 97 + c] = QKV[(size_t)(start + r) * QKVD + DMODEL + h * HD + c];
    }
    __syncthreads();

    const float scale = 0.10206207261596575f;   // 1/sqrt(96)

    for (int qi = warp; qi < len; qi += 4) {
        for (int c = lane; c < HD; c += 32)
            Qs[warp][c] = QKV[(size_t)(start + qi) * QKVD + h * HD + c];
        __syncwarp();

        float sj[3];
        float mx = -1e30f;
#pragma unroll
        for (int u = 0; u < 3; u++) {
            int j = lane + 32 * u;
            float d = 0.f;
            if (j < len) {
                const float* kr = &Ks[j * 97];
#pragma unroll
                for (int c = 0; c < HD; c++) d = fmaf(Qs[warp][c], kr[c], d);
                d *= scale;
                mx = fmaxf(mx, d);
            }
            sj[u] = d;
        }
        for (int o = 16; o > 0; o >>= 1) mx = fmaxf(mx, __shfl_xor_sync(0xffffffffu, mx, o));
        float sum = 0.f;
#pragma unroll
        for (int u = 0; u < 3; u++) {
            int j = lane + 32 * u;
            float p = 0.f;
            if (j < len) p = expf(sj[u] - mx);
            sj[u] = p; sum += p;
        }
        for (int o = 16; o > 0; o >>= 1) sum += __shfl_xor_sync(0xffffffffu, sum, o);
        float inv = 1.f / sum;
#pragma unroll
        for (int u = 0; u < 3; u++) {
            int j = lane + 32 * u;
            if (j < len) Pw[warp][j] = sj[u] * inv;
        }
        __syncwarp();

#pragma unroll
        for (int u = 0; u < 3; u++) {
            int dcol = lane + 32 * u;
            float acc = 0.f;
            for (int j = 0; j < len; j++)
                acc = fmaf(Pw[warp][j],
                           QKV[(size_t)(start + j) * QKVD + 2 * DMODEL + h * HD + dcol], acc);
            ATT[(size_t)(start + qi) * DMODEL + h * HD + dcol] = acc;
        }
        __syncwarp();
    }
}

// ---------------- layernorm: one block per row ----------------
__global__ void ln_kernel(const float* __restrict__ in, const float* __restrict__ g,
                          const float* __restrict__ b, float* __restrict__ out)
{
    __shared__ float red[16];
    int r = blockIdx.x, tid = threadIdx.x;   // 256 threads
    const float* x = in + (size_t)r * DMODEL;
    float v0 = x[tid], v1 = x[tid + 256], v2 = x[tid + 512];
    float s = v0 + v1 + v2;
    float ss = v0 * v0 + v1 * v1 + v2 * v2;
    for (int o = 16; o > 0; o >>= 1) {
        s  += __shfl_xor_sync(0xffffffffu, s, o);
        ss += __shfl_xor_sync(0xffffffffu, ss, o);
    }
    int warp = tid >> 5, lane = tid & 31;
    if (lane == 0) { red[warp] = s; red[warp + 8] = ss; }
    __syncthreads();
    if (tid < 32) {
        float a = (tid < 8) ? red[tid] : 0.f;
        float c = (tid < 8) ? red[tid + 8] : 0.f;
        for (int o = 4; o > 0; o >>= 1) {
            a += __shfl_xor_sync(0xffffffffu, a, o);
            c += __shfl_xor_sync(0xffffffffu, c, o);
        }
        if (tid == 0) { red[0] = a; red[1] = c; }
    }
    __syncthreads();
    float mean = red[0] * (1.f / DMODEL);
    float var  = red[1] * (1.f / DMODEL) - mean * mean;
    float inv  = rsqrtf(var + 1e-5f);
    float* o = out + (size_t)r * DMODEL;
    o[tid]       = (v0 - mean) * inv * g[tid]       + b[tid];
    o[tid + 256] = (v1 - mean) * inv * g[tid + 256] + b[tid + 256];
    o[tid + 512] = (v2 - mean) * inv * g[tid + 512] + b[tid + 512];
}

// ---------------- pooler ----------------
__global__ void pool_kernel(const float* __restrict__ X, const float* __restrict__ X0q,
                            const float* __restrict__ cls_topic,
                            const float* __restrict__ W, const float* __restrict__ bias,
                            const float* __restrict__ mixer, float* __restrict__ PV)
{
    int i = blockIdx.x, tid = threadIdx.x;  // 32 blocks x 256
    __shared__ float xin[DMODEL];
    float mx = mixer[0];
    for (int k = tid; k < DMODEL; k += 256) {
        float pre, post;
        if (i < BQ) {
            pre  = X0q[(size_t)i * DMODEL + k];
            post = X[(size_t)(QL * i) * DMODEL + k];
        } else {
            pre  = cls_topic[k];
            post = X[(size_t)(BQ * QL + DSEQ * (i - BQ)) * DMODEL + k];
        }
        xin[k] = mx * pre + (1.f - mx) * post;
    }
    __syncthreads();
    for (int n = tid; n < DMODEL; n += 256) {
        const float* w = W + (size_t)n * DMODEL;
        float acc = bias[n];
        for (int k = 0; k < DMODEL; k++) acc = fmaf(xin[k], w[k], acc);
        PV[(size_t)i * DMODEL + n] = acc;
    }
}

// ---------------- normalize & scatter ----------------
__global__ void norm_kernel(const float* __restrict__ PV, float* __restrict__ out)
{
    __shared__ float red[8];
    int i = blockIdx.x, tid = threadIdx.x;  // 32 blocks x 256
    const float* x = PV + (size_t)i * DMODEL;
    float ss = 0.f;
    for (int k = tid; k < DMODEL; k += 256) { float v = x[k]; ss += v * v; }
    for (int o = 16; o > 0; o >>= 1) ss += __shfl_xor_sync(0xffffffffu, ss, o);
    int warp = tid >> 5, lane = tid & 31;
    if (lane == 0) red[warp] = ss;
    __syncthreads();
    if (tid < 32) {
        float a = (tid < 8) ? red[tid] : 0.f;
        for (int o = 4; o > 0; o >>= 1) a += __shfl_xor_sync(0xffffffffu, a, o);
        if (tid == 0) red[0] = a;
    }
    __syncthreads();
    float inv = 1.f / (sqrtf(red[0]) + 1e-4f);
    float* dst = out + 16 + ((i < BQ) ? (size_t)i * DMODEL
                                      : (size_t)BQ * DMODEL + (size_t)(i - BQ) * DMODEL);
    for (int k = tid; k < DMODEL; k += 256) dst[k] = x[k] * inv;
}

__global__ void score_kernel(float* __restrict__ out)
{
    __shared__ float red[8];
    int b = blockIdx.x, tid = threadIdx.x;  // 16 blocks x 256
    const float* q = out + 16 + (size_t)b * DMODEL;
    const float* d = out + 16 + (size_t)BQ * DMODEL + (size_t)b * DMODEL;
    float s = 0.f;
    for (int k = tid; k < DMODEL; k += 256) s = fmaf(q[k], d[k], s);
    for (int o = 16; o > 0; o >>= 1) s += __shfl_xor_sync(0xffffffffu, s, o);
    int warp = tid >> 5, lane = tid & 31;
    if (lane == 0) red[warp] = s;
    __syncthreads();
    if (tid == 0) {
        float t = 0.f;
        for (int w = 0; w < 8; w++) t += red[w];
        out[b] = 6.f * t;
    }
}

// ---------------- launch ----------------
extern "C" void kernel_launch(void* const* d_in, const int* in_sizes, int n_in,
                              void* d_out, int out_size)
{
    const float* emb       = (const float*)d_in[0];
    const float* pos_q     = (const float*)d_in[1];
    const float* pos_d     = (const float*)d_in[2];
    const float* cls_topic = (const float*)d_in[3];
    const float* mixer     = (const float*)d_in[4];
    const float* pw        = (const float*)d_in[5];
    const float* pb        = (const float*)d_in[6];
    const float* Wqkv      = (const float*)d_in[7];
    const float* bqkv      = (const float*)d_in[8];
    const float* Wo        = (const float*)d_in[9];
    const float* bo        = (const float*)d_in[10];
    const float* g1        = (const float*)d_in[11];
    const float* b1        = (const float*)d_in[12];
    const float* W1        = (const float*)d_in[13];
    const float* bf1       = (const float*)d_in[14];
    const float* W2        = (const float*)d_in[15];
    const float* bf2       = (const float*)d_in[16];
    const float* g2        = (const float*)d_in[17];
    const float* b2        = (const float*)d_in[18];
    const int*   query     = (const int*)d_in[19];
    const int*   document  = (const int*)d_in[20];
    float* out = (float*)d_out;

    float *X, *X0, *QKV, *ATT, *TMP, *Hb, *PV;
    uint2 *WqkvSP, *WoSP, *W1SP, *W2SP, *ACT;
    cudaGetSymbolAddress((void**)&X,   g_X);
    cudaGetSymbolAddress((void**)&X0,  g_X0q);
    cudaGetSymbolAddress((void**)&QKV, g_QKV);
    cudaGetSymbolAddress((void**)&ATT, g_ATT);
    cudaGetSymbolAddress((void**)&TMP, g_TMP);
    cudaGetSymbolAddress((void**)&Hb,  g_H);
    cudaGetSymbolAddress((void**)&PV,  g_PV);
    cudaGetSymbolAddress((void**)&WqkvSP, g_WqkvSP);
    cudaGetSymbolAddress((void**)&WoSP,   g_WoSP);
    cudaGetSymbolAddress((void**)&W1SP,   g_W1SP);
    cudaGetSymbolAddress((void**)&W2SP,   g_W2SP);
    cudaGetSymbolAddress((void**)&ACT,    g_ACT);

    // weight pre-splits (whole 2-layer tensors)
    split_kernel<<<(2*DMODEL*QKVD)/1024, 256>>>(Wqkv, WqkvSP, 2*DMODEL*QKVD);
    split_kernel<<<(2*DMODEL*DMODEL)/1024, 256>>>(Wo, WoSP, 2*DMODEL*DMODEL);
    split_kernel<<<(2*DMODEL*FFD)/1024, 256>>>(W1, W1SP, 2*DMODEL*FFD);
    split_kernel<<<(2*FFD*DMODEL)/1024, 256>>>(W2, W2SP, 2*FFD*DMODEL);

    embed_kernel<<<NTOK, 256>>>(emb, pos_q, pos_d, cls_topic, query, document, X, X0);

    const int MB = NTOKP / 64;   // 24
    for (int l = 0; l < 2; l++) {
        const uint2* wqkv = WqkvSP + (size_t)l * DMODEL * QKVD;
        const uint2* wo   = WoSP   + (size_t)l * DMODEL * DMODEL;
        const uint2* w1   = W1SP   + (size_t)l * DMODEL * FFD;
        const uint2* w2   = W2SP   + (size_t)l * FFD * DMODEL;

        split_kernel<<<(NTOKP*DMODEL)/1024, 256>>>(X, ACT, NTOKP*DMODEL);
        gemm_ts<false, false><<<dim3(QKVD / 64, MB), 256>>>(
            ACT, wqkv, bqkv + (size_t)l * QKVD, nullptr, QKV, NTOK, QKVD, DMODEL);

        attn_kernel<<<dim3(32, NH), 128>>>(QKV, ATT);

        split_kernel<<<(NTOKP*DMODEL)/1024, 256>>>(ATT, ACT, NTOKP*DMODEL);
        gemm_ts<false, true><<<dim3(DMODEL / 64, MB), 256>>>(
            ACT, wo, bo + (size_t)l * DMODEL, X, TMP, NTOK, DMODEL, DMODEL);

        ln_kernel<<<NTOK, 256>>>(TMP, g1 + (size_t)l * DMODEL, b1 + (size_t)l * DMODEL, X);

        split_kernel<<<(NTOKP*DMODEL)/1024, 256>>>(X, ACT, NTOKP*DMODEL);
        gemm_ts<true, false><<<dim3(FFD / 64, MB), 256>>>(
            ACT, w1, bf1 + (size_t)l * FFD, nullptr, Hb, NTOK, FFD, DMODEL);

        split_kernel<<<(NTOKP*FFD)/1024, 256>>>(Hb, ACT, NTOKP*FFD);
        gemm_ts<false, true><<<dim3(DMODEL / 64, MB), 256>>>(
            ACT, w2, bf2 + (size_t)l * DMODEL, X, TMP, NTOK, DMODEL, FFD);

        ln_kernel<<<NTOK, 256>>>(TMP, g2 + (size_t)l * DMODEL, b2 + (size_t)l * DMODEL, X);
    }

    pool_kernel<<<32, 256>>>(X, X0, cls_topic, pw, pb, mixer, PV);
    norm_kernel<<<32, 256>>>(PV, out);
    score_kernel<<<16, 256>>>(out);
}